// round 17
// baseline (speedup 1.0000x reference)
#include <cuda_runtime.h>
#include <cuda_fp16.h>
#include <cstdint>

#define Hd 128
#define MAXM 50048
#define MAXL 400128
#define SEPS 1e-9f
#define NT 512

// ---------------- scratch (device globals; no allocations) ----------------
__device__ float g_hhat[MAXM*Hd];
__device__ float g_sumfc[MAXM*Hd];
// fp16 GEMM outputs / pair operands
__device__ __half g_Ahh [MAXM*Hd];
__device__ __half g_Bxh [MAXM*Hd];
__device__ __half g_Wfxh[MAXM*Hd];
__device__ __half g_Ufhh[MAXM*Hd];
__device__ __half g_Wixh[MAXM*Hd];
__device__ __half g_Woxh[MAXM*Hd];
__device__ __half g_Wcxh[MAXM*Hd];
__device__ __half g_Uihh[MAXM*Hd];
__device__ __half g_Uchh[MAXM*Hd];
__device__ __half g_Uohh[MAXM*Hd];
__device__ __half g_chh [MAXM*Hd];   // fp16 shadow of child_h
__device__ __half g_cch [MAXM*Hd];   // fp16 shadow of child_c
// counting sort of pairs by ci
__device__ int g_cnt[MAXM];
__device__ int g_off[MAXM];
__device__ int g_cursor[MAXM];
__device__ int g_blk[64];
__device__ int g_sorted[MAXL];
// pre-swizzled single-fp16 weights: 10 x 128x128, 32KB each
__device__ __align__(16) char g_Wbh[10 * 32768];

// ---------------- scalar helpers ----------------
__device__ __forceinline__ float sigm_f(float x) {
    return __fdividef(1.0f, 1.0f + __expf(-x));
}
__device__ __forceinline__ float tanh_f(float x) {
    float e2 = __expf(2.0f * x);
    return 1.0f - __fdividef(2.0f, e2 + 1.0f);
}
__device__ __forceinline__ uint32_t smem_u32(const void* p) {
    uint32_t a;
    asm("{ .reg .u64 t; cvta.to.shared.u64 t, %1; cvt.u32.u64 %0, t; }" : "=r"(a) : "l"(p));
    return a;
}
__device__ __forceinline__ float4 ld_half4(const __half* p) {
    uint2 v = *(const uint2*)p;
    float2 lo = __half22float2(*(__half2*)&v.x);
    float2 hi = __half22float2(*(__half2*)&v.y);
    return make_float4(lo.x, lo.y, hi.x, hi.y);
}
__device__ __forceinline__ uint32_t packh2(float x, float y) {
    __half2 h = __floats2half2_rn(x, y);
    return *(uint32_t*)&h;
}

// ---------------- cp.async helpers ----------------
__device__ __forceinline__ void cpasync16(uint32_t saddr, const void* g) {
    asm volatile("cp.async.cg.shared.global [%0], [%1], 16;" :: "r"(saddr), "l"(g));
}
#define CP_COMMIT() asm volatile("cp.async.commit_group;" ::: "memory")
#define CP_WAIT0()  asm volatile("cp.async.wait_group 0;" ::: "memory")

// ---------------- mma / ldmatrix wrappers ----------------
__device__ __forceinline__ void ldm4(uint32_t* r, uint32_t addr) {
    asm volatile("ldmatrix.sync.aligned.m8n8.x4.shared.b16 {%0,%1,%2,%3}, [%4];"
                 : "=r"(r[0]), "=r"(r[1]), "=r"(r[2]), "=r"(r[3]) : "r"(addr));
}
__device__ __forceinline__ void mma16816h(float* d, const uint32_t* a, const uint32_t* b) {
    asm volatile("mma.sync.aligned.m16n8k16.row.col.f32.f16.f16.f32 "
                 "{%0,%1,%2,%3}, {%4,%5,%6,%7}, {%8,%9}, {%0,%1,%2,%3};"
                 : "+f"(d[0]), "+f"(d[1]), "+f"(d[2]), "+f"(d[3])
                 : "r"(a[0]), "r"(a[1]), "r"(a[2]), "r"(a[3]), "r"(b[0]), "r"(b[1]));
}

// swizzled byte offset of (row, colbyte) in a 128-row x 256B tile
__device__ __forceinline__ uint32_t swz(int row, int colbyte) {
    return (uint32_t)(row * 256 + (colbyte ^ ((row & 7) << 4)));
}

// ---------------- main-stream prep: fp16 weights only ----------------
struct PrepArgs { const float* W[10]; };

__global__ void prep_w_kernel(PrepArgs pa) {
    int stride = gridDim.x * blockDim.x;
    int gt = blockIdx.x * blockDim.x + threadIdx.x;
    for (int idx = gt; idx < 10 * 8192; idx += stride) {
        int w = idx >> 13;
        int i = idx & 8191;
        int row = i >> 6;
        int c2 = i & 63;
        float2 v = *(const float2*)(pa.W[w] + (size_t)row * Hd + c2 * 2);
        *(uint32_t*)(g_Wbh + w * 32768 + swz(row, c2 * 4)) = packh2(v.x, v.y);
    }
}

// ---------------- side-stream: zero counters + fp16 shadows ----------------
__global__ void side_kernel(const float* __restrict__ child_h,
                            const float* __restrict__ child_c, int M) {
    int stride = gridDim.x * blockDim.x;
    int gt = blockIdx.x * blockDim.x + threadIdx.x;
    for (int i = gt; i < MAXM; i += stride) g_cnt[i] = 0;
    int n2 = M * Hd / 2;
    for (int i = gt; i < n2; i += stride) {
        float2 vh = ((const float2*)child_h)[i];
        float2 vc = ((const float2*)child_c)[i];
        ((__half2*)g_chh)[i] = __floats2half2_rn(vh.x, vh.y);
        ((__half2*)g_cch)[i] = __floats2half2_rn(vc.x, vc.y);
    }
}

// ---------------- counting sort of pairs by ci ----------------
__global__ void hist_kernel(const int* __restrict__ ci, int L) {
    int stride = gridDim.x * blockDim.x;
    for (int l = blockIdx.x * blockDim.x + threadIdx.x; l < L; l += stride)
        atomicAdd(&g_cnt[ci[l]], 1);
}

// per-1024-block exclusive scan; 256 threads, 4 elems/thread
__global__ void scan1_kernel() {
    __shared__ int warp_tot[8];
    __shared__ int warp_off[8];
    int t = threadIdx.x;
    int lane = t & 31;
    int wid = t >> 5;
    int base = blockIdx.x * 1024 + t * 4;
    int v0 = base + 0 < MAXM ? g_cnt[base + 0] : 0;
    int v1 = base + 1 < MAXM ? g_cnt[base + 1] : 0;
    int v2 = base + 2 < MAXM ? g_cnt[base + 2] : 0;
    int v3 = base + 3 < MAXM ? g_cnt[base + 3] : 0;
    int p1 = v0, p2 = v0 + v1, p3 = v0 + v1 + v2;
    int tsum = p3 + v3;
    int x = tsum;
#pragma unroll
    for (int o = 1; o < 32; o <<= 1) {
        int y = __shfl_up_sync(0xFFFFFFFFu, x, o);
        if (lane >= o) x += y;
    }
    if (lane == 31) warp_tot[wid] = x;
    __syncthreads();
    if (t == 0) {
        int r = 0;
#pragma unroll
        for (int i = 0; i < 8; i++) { warp_off[i] = r; r += warp_tot[i]; }
        g_blk[blockIdx.x] = r;
    }
    __syncthreads();
    int excl = x - tsum + warp_off[wid];
    if (base + 0 < MAXM) g_off[base + 0] = excl;
    if (base + 1 < MAXM) g_off[base + 1] = excl + p1;
    if (base + 2 < MAXM) g_off[base + 2] = excl + p2;
    if (base + 3 < MAXM) g_off[base + 3] = excl + p3;
}

// parallel scan of block totals (single warp, 2 elems/lane)
__global__ void scan2_kernel(int nblk) {
    int lane = threadIdx.x;
    int v0 = lane * 2 + 0 < nblk ? g_blk[lane * 2 + 0] : 0;
    int v1 = lane * 2 + 1 < nblk ? g_blk[lane * 2 + 1] : 0;
    int tsum = v0 + v1;
    int x = tsum;
#pragma unroll
    for (int o = 1; o < 32; o <<= 1) {
        int y = __shfl_up_sync(0xFFFFFFFFu, x, o);
        if (lane >= o) x += y;
    }
    int excl = x - tsum;
    if (lane * 2 + 0 < nblk) g_blk[lane * 2 + 0] = excl;
    if (lane * 2 + 1 < nblk) g_blk[lane * 2 + 1] = excl + v0;
}

__global__ void fixup_kernel() {
    int stride = gridDim.x * blockDim.x;
    for (int i = blockIdx.x * blockDim.x + threadIdx.x; i < MAXM; i += stride) {
        int o = g_off[i] + g_blk[i >> 10];
        g_off[i] = o;
        g_cursor[i] = o;
    }
}

__global__ void scatter_kernel(const int* __restrict__ ci, int L) {
    int stride = gridDim.x * blockDim.x;
    for (int l = blockIdx.x * blockDim.x + threadIdx.x; l < L; l += stride) {
        int pos = atomicAdd(&g_cursor[ci[l]], 1);
        g_sorted[pos] = l;
    }
}

// ---------------- seg_attn: online-softmax attention -> h_hat ----------------
__global__ void seg_attn_kernel(const int* __restrict__ chi, const float* __restrict__ v,
                                int M) {
    __shared__ float vs[Hd];
    if (threadIdx.x < Hd) vs[threadIdx.x] = v[threadIdx.x];
    __syncthreads();

    int m = blockIdx.x * (blockDim.x >> 5) + (threadIdx.x >> 5);
    int lane = threadIdx.x & 31;
    if (m >= M) return;

    int start = __ldg(g_off + m);
    int end   = __ldg(g_cursor + m);   // after scatter, cursor == segment end

    size_t mo = (size_t)m * Hd + lane * 4;
    float4 vv = *(const float4*)(vs + lane * 4);
    float4 bx = ld_half4(g_Bxh + mo);

    float runm = -3.4e38f, s = 0.f;
    float4 acch = make_float4(0.f, 0.f, 0.f, 0.f);

    for (int p = start; p < end; p++) {
        int l = __ldg(g_sorted + p);
        int ch = __ldg(chi + l);
        size_t cho = (size_t)ch * Hd + lane * 4;

        float4 a = ld_half4(g_Ahh + cho);
        float e = tanh_f(a.x + bx.x) * vv.x + tanh_f(a.y + bx.y) * vv.y +
                  tanh_f(a.z + bx.z) * vv.z + tanh_f(a.w + bx.w) * vv.w;
#pragma unroll
        for (int o = 16; o; o >>= 1) e += __shfl_xor_sync(0xFFFFFFFFu, e, o);

        float mnew = fmaxf(runm, e);
        float scale = __expf(runm - mnew);   // 0 on first pair (runm = -big)
        float xe = __expf(e - mnew);
        s = s * scale + xe;

        float4 hv = ld_half4(g_chh + cho);
        acch.x = acch.x * scale + xe * hv.x;
        acch.y = acch.y * scale + xe * hv.y;
        acch.z = acch.z * scale + xe * hv.z;
        acch.w = acch.w * scale + xe * hv.w;

        runm = mnew;
    }

    float inv = __fdividef(1.0f, s + SEPS);
    *(float4*)(g_hhat + mo) =
        make_float4(acch.x * inv, acch.y * inv, acch.z * inv, acch.w * inv);
}

// ---------------- seg_forget: forget-gate accumulation -> sumfc ----------------
__global__ void seg_forget_kernel(const int* __restrict__ chi, int M) {
    int m = blockIdx.x * (blockDim.x >> 5) + (threadIdx.x >> 5);
    int lane = threadIdx.x & 31;
    if (m >= M) return;

    int start = __ldg(g_off + m);
    int end   = __ldg(g_cursor + m);

    size_t mo = (size_t)m * Hd + lane * 4;
    float4 wf = ld_half4(g_Wfxh + mo);
    float4 accf = make_float4(0.f, 0.f, 0.f, 0.f);

    for (int p = start; p < end; p++) {
        int l = __ldg(g_sorted + p);
        int ch = __ldg(chi + l);
        size_t cho = (size_t)ch * Hd + lane * 4;

        float4 uf = ld_half4(g_Ufhh + cho);
        float4 cv = ld_half4(g_cch + cho);
        accf.x += sigm_f(wf.x + uf.x) * cv.x;
        accf.y += sigm_f(wf.y + uf.y) * cv.y;
        accf.z += sigm_f(wf.z + uf.z) * cv.z;
        accf.w += sigm_f(wf.w + uf.w) * cv.w;
    }
    *(float4*)(g_sumfc + mo) = accf;
}

// ---------------- shared GEMM building blocks ----------------
#define SA    0
#define SW0   32768
#define S_TOT1 (32768 * 3)

__device__ __forceinline__ void conv_tile(const float* __restrict__ A, int m0, int M,
                                          char* dst, int tid) {
#pragma unroll
    for (int it = 0; it < 8192 / NT; it++) {
        int i = tid + it * NT;
        int row = i >> 6;
        int c2 = i & 63;
        float2 v = make_float2(0.f, 0.f);
        if (m0 + row < M) v = *(const float2*)(A + (size_t)(m0 + row) * Hd + c2 * 2);
        *(uint32_t*)(dst + swz(row, c2 * 4)) = packh2(v.x, v.y);
    }
}

// async fetch of one 32KB weight tile into smem buffer
__device__ __forceinline__ void prefetch_w(uint32_t sbuf, const char* wh, int tid) {
#pragma unroll
    for (int it = 0; it < 2048 / NT; it++) {
        int i = tid + it * NT;
        cpasync16(sbuf + i * 16, wh + i * 16);
    }
    CP_COMMIT();
}

// compute 128x128 fp16 gemm tile into acc[2][4][4]
__device__ __forceinline__ void gemm_core(const uint32_t smb, uint32_t swoff,
                                          float acc[2][4][4],
                                          int arow0, int akb, int brow0, int bkb) {
#pragma unroll
    for (int ti = 0; ti < 2; ti++)
#pragma unroll
        for (int tj = 0; tj < 4; tj++)
#pragma unroll
            for (int k = 0; k < 4; k++) acc[ti][tj][k] = 0.f;

#pragma unroll
    for (int ks = 0; ks < 8; ks++) {
        const int kb0 = ks * 32;
        uint32_t ah[2][4], bh[2][4];
#pragma unroll
        for (int ti = 0; ti < 2; ti++) {
            int row = arow0 + ti * 16;
            ldm4(ah[ti], smb + SA + swz(row, kb0 + akb));
        }
#pragma unroll
        for (int tp = 0; tp < 2; tp++) {
            int row = brow0 + tp * 16;
            ldm4(bh[tp], smb + swoff + swz(row, kb0 + bkb));
        }
#pragma unroll
        for (int ti = 0; ti < 2; ti++)
#pragma unroll
            for (int tj = 0; tj < 4; tj++) {
                const uint32_t* bp = &bh[tj >> 1][(tj & 1) * 2];
                mma16816h(acc[ti][tj], ah[ti], bp);
            }
    }
}

// ---------------- batched GEMM: fp16 outputs, double-buffered weights ----------------
struct TcArgs {
    const float* A1;
    const float* A2;
    const char* wh[7];
    const float* b[7];
    __half* C[7];
    int nW1, nW2, M;
};

__global__ void __launch_bounds__(NT, 1) gemm_mma(TcArgs ga) {
    extern __shared__ char sm[];
    const uint32_t smb = smem_u32(sm);
    const int tid = threadIdx.x;
    const int wid = tid >> 5;
    const int lane = tid & 31;
    const int m0 = blockIdx.x * 128;
    const int M = ga.M;
    const int wm = wid >> 2;
    const int wn = wid & 3;
    const int sub = lane & 7;
    const int quad = lane >> 3;
    const int arow0 = wm * 32 + sub + (quad & 1) * 8;
    const int akb   = (quad >> 1) * 16;
    const int brow0 = wn * 32 + sub + (quad >> 1) * 8;
    const int bkb   = (quad & 1) * 16;
    const int g = lane >> 2;
    const int tg = lane & 3;

    const int nWtot = ga.nW1 + ga.nW2;

    // prologue: async-fetch weight 0, convert first A tile
    prefetch_w(smb + SW0, ga.wh[0], tid);
    conv_tile(ga.A1, m0, M, sm + SA, tid);

    int cur = 0;
    for (int w = 0; w < nWtot; w++) {
        CP_WAIT0();
        __syncthreads();                  // weight buf(cur) + A tile visible

        if (w == ga.nW1) {
            // switch A operand to A2 (prior gemm readers of SA passed the sync)
            conv_tile(ga.A2, m0, M, sm + SA, tid);
        }
        if (w + 1 < nWtot)
            prefetch_w(smb + SW0 + (cur ^ 1) * 32768, ga.wh[w + 1], tid);
        if (w == ga.nW1)
            __syncthreads();              // new A tile visible

        float acc[2][4][4];
        gemm_core(smb, SW0 + cur * 32768, acc, arow0, akb, brow0, bkb);

        // store fp16 C tile (+bias via __ldg; bias is 512B, L2-broadcast)
        const float* bias = ga.b[w];
        __half* __restrict__ C = ga.C[w];
#pragma unroll
        for (int ti = 0; ti < 2; ti++)
#pragma unroll
            for (int tj = 0; tj < 4; tj++) {
                int row = m0 + wm * 32 + ti * 16 + g;
                int col = wn * 32 + tj * 8 + tg * 2;
                float2 bv = bias ? *(const float2*)(bias + col) : make_float2(0.f, 0.f);
                if (row < M)
                    *(__half2*)(C + (size_t)row * Hd + col) =
                        __floats2half2_rn(acc[ti][tj][0] + bv.x, acc[ti][tj][1] + bv.y);
                if (row + 8 < M)
                    *(__half2*)(C + (size_t)(row + 8) * Hd + col) =
                        __floats2half2_rn(acc[ti][tj][2] + bv.x, acc[ti][tj][3] + bv.y);
            }
        cur ^= 1;
        __syncthreads();                  // all reads of buf(cur^1) done before its refill next iter
    }
}

// ---------------- epilogue: gates -> h, c ----------------
__global__ void epilogue_kernel(float* __restrict__ outh, float* __restrict__ outc, int n4) {
    int stride = gridDim.x * blockDim.x;
    for (int i = blockIdx.x * blockDim.x + threadIdx.x; i < n4; i += stride) {
        size_t e = (size_t)i * 4;
        float4 wix = ld_half4(g_Wixh + e);
        float4 uih = ld_half4(g_Uihh + e);
        float4 wcx = ld_half4(g_Wcxh + e);
        float4 uch = ld_half4(g_Uchh + e);
        float4 wox = ld_half4(g_Woxh + e);
        float4 uoh = ld_half4(g_Uohh + e);
        float4 sf  = ((const float4*)g_sumfc)[i];

        float4 hc, cc;
        {
            float ig = sigm_f(wix.x + uih.x);
            float ct = tanh_f(wcx.x + uch.x);
            float cval = fmaf(ig, ct, sf.x);
            float og = sigm_f(wox.x + uoh.x);
            cc.x = cval; hc.x = og * tanh_f(cval);
        }
        {
            float ig = sigm_f(wix.y + uih.y);
            float ct = tanh_f(wcx.y + uch.y);
            float cval = fmaf(ig, ct, sf.y);
            float og = sigm_f(wox.y + uoh.y);
            cc.y = cval; hc.y = og * tanh_f(cval);
        }
        {
            float ig = sigm_f(wix.z + uih.z);
            float ct = tanh_f(wcx.z + uch.z);
            float cval = fmaf(ig, ct, sf.z);
            float og = sigm_f(wox.z + uoh.z);
            cc.z = cval; hc.z = og * tanh_f(cval);
        }
        {
            float ig = sigm_f(wix.w + uih.w);
            float ct = tanh_f(wcx.w + uch.w);
            float cval = fmaf(ig, ct, sf.w);
            float og = sigm_f(wox.w + uoh.w);
            cc.w = cval; hc.w = og * tanh_f(cval);
        }
        ((float4*)outh)[i] = hc;
        ((float4*)outc)[i] = cc;
    }
}

// ---------------- launch ----------------
extern "C" void kernel_launch(void* const* d_in, const int* in_sizes, int n_in,
                              void* d_out, int out_size) {
    const float* x_emb   = (const float*)d_in[0];
    const float* child_h = (const float*)d_in[1];
    const float* child_c = (const float*)d_in[2];
    const int*   ci      = (const int*)d_in[3];
    const int*   chi     = (const int*)d_in[4];
    const float* Wi_w = (const float*)d_in[5];
    const float* Ui_w = (const float*)d_in[6];
    const float* Wf_w = (const float*)d_in[7];
    const float* Uf_w = (const float*)d_in[8];
    const float* Wo_w = (const float*)d_in[9];
    const float* Uo_w = (const float*)d_in[10];
    const float* Wc_w = (const float*)d_in[11];
    const float* Uc_w = (const float*)d_in[12];
    const float* Wa_w = (const float*)d_in[13];
    const float* Ua_w = (const float*)d_in[14];
    const float* Wi_b = (const float*)d_in[15];
    const float* Wf_b = (const float*)d_in[16];
    const float* Wo_b = (const float*)d_in[17];
    const float* Wc_b = (const float*)d_in[18];
    const float* Wa_b = (const float*)d_in[19];
    const float* v_w  = (const float*)d_in[20];

    const int M = in_sizes[0] / Hd;
    const int L = in_sizes[3];

    float *p_hhat;
    cudaGetSymbolAddress((void**)&p_hhat, g_hhat);
    __half *p_Ahh, *p_Bxh, *p_Wfxh, *p_Ufhh, *p_Wixh, *p_Woxh, *p_Wcxh, *p_Uihh, *p_Uchh, *p_Uohh;
    cudaGetSymbolAddress((void**)&p_Ahh,  g_Ahh);
    cudaGetSymbolAddress((void**)&p_Bxh,  g_Bxh);
    cudaGetSymbolAddress((void**)&p_Wfxh, g_Wfxh);
    cudaGetSymbolAddress((void**)&p_Ufhh, g_Ufhh);
    cudaGetSymbolAddress((void**)&p_Wixh, g_Wixh);
    cudaGetSymbolAddress((void**)&p_Woxh, g_Woxh);
    cudaGetSymbolAddress((void**)&p_Wcxh, g_Wcxh);
    cudaGetSymbolAddress((void**)&p_Uihh, g_Uihh);
    cudaGetSymbolAddress((void**)&p_Uchh, g_Uchh);
    cudaGetSymbolAddress((void**)&p_Uohh, g_Uohh);
    char *p_wh;
    cudaGetSymbolAddress((void**)&p_wh, g_Wbh);

    float* outh = (float*)d_out;
    float* outc = outh + (size_t)M * Hd;

    const int mtiles = (M + 127) / 128;
    const int nblk = (MAXM + 1023) / 1024;

    cudaFuncSetAttribute(gemm_mma, cudaFuncAttributeMaxDynamicSharedMemorySize, S_TOT1);

    // one-time side stream + events (host resources; identical work per call)
    static cudaStream_t s2 = nullptr;
    static cudaEvent_t evF = nullptr, evSort = nullptr, evPW = nullptr, evFG = nullptr;
    if (!s2) {
        cudaStreamCreateWithFlags(&s2, cudaStreamNonBlocking);
        cudaEventCreateWithFlags(&evF,    cudaEventDisableTiming);
        cudaEventCreateWithFlags(&evSort, cudaEventDisableTiming);
        cudaEventCreateWithFlags(&evPW,   cudaEventDisableTiming);
        cudaEventCreateWithFlags(&evFG,   cudaEventDisableTiming);
    }

    // fork: side stream does shadows + counting sort
    cudaEventRecord(evF, 0);
    cudaStreamWaitEvent(s2, evF, 0);
    side_kernel<<<296, 256, 0, s2>>>(child_h, child_c, M);
    hist_kernel<<<296, 256, 0, s2>>>(ci, L);
    scan1_kernel<<<nblk, 256, 0, s2>>>();
    scan2_kernel<<<1, 32, 0, s2>>>(nblk);
    fixup_kernel<<<64, 256, 0, s2>>>();
    scatter_kernel<<<296, 256, 0, s2>>>(ci, L);
    cudaEventRecord(evSort, s2);

    // main stream: weights prep
    {
        PrepArgs pa;
        pa.W[0] = Ua_w; pa.W[1] = Wi_w; pa.W[2] = Wf_w; pa.W[3] = Wo_w; pa.W[4] = Wc_w;
        pa.W[5] = Wa_w; pa.W[6] = Uf_w; pa.W[7] = Ui_w; pa.W[8] = Uc_w; pa.W[9] = Uo_w;
        prep_w_kernel<<<148, 256>>>(pa);
    }
    cudaEventRecord(evPW, 0);

    // main stream: GEMM1a — only what seg_attn needs (Bx from Ua, Ah from Wa)
    {
        TcArgs ga;
        ga.A1 = x_emb; ga.A2 = child_h; ga.nW1 = 1; ga.nW2 = 1; ga.M = M;
        int slot[7] = {0, 5, 0, 0, 0, 0, 0};
        const float* bs[7] = {nullptr, Wa_b, nullptr, nullptr, nullptr, nullptr, nullptr};
        __half* cs[7] = {p_Bxh, p_Ahh, p_Bxh, p_Bxh, p_Bxh, p_Bxh, p_Bxh};
        for (int i = 0; i < 7; i++) {
            ga.wh[i] = p_wh + slot[i] * 32768;
            ga.b[i] = bs[i];
            ga.C[i] = cs[i];
        }
        gemm_mma<<<mtiles, NT, S_TOT1>>>(ga);
    }

    // side stream: GEMM1b (Wix/Wfx/Wox/Wcx + Ufh) after sort + weight prep,
    // concurrent with main's seg_attn / GEMM3 (tensor vs memory pipes)
    cudaStreamWaitEvent(s2, evPW, 0);
    {
        TcArgs ga;
        ga.A1 = x_emb; ga.A2 = child_h; ga.nW1 = 4; ga.nW2 = 1; ga.M = M;
        int slot[7] = {1, 2, 3, 4, 6, 0, 0};
        const float* bs[7] = {Wi_b, Wf_b, Wo_b, Wc_b, nullptr, nullptr, nullptr};
        __half* cs[7] = {p_Wixh, p_Wfxh, p_Woxh, p_Wcxh, p_Ufhh, p_Bxh, p_Bxh};
        for (int i = 0; i < 7; i++) {
            ga.wh[i] = p_wh + slot[i] * 32768;
            ga.b[i] = bs[i];
            ga.C[i] = cs[i];
        }
        gemm_mma<<<mtiles, NT, S_TOT1, s2>>>(ga);
    }
    // side stream: seg_forget (needs GEMM1b outputs + shadows + sort, all stream-ordered)
    seg_forget_kernel<<<(M + 7) / 8, 256, 0, s2>>>(chi, M);
    cudaEventRecord(evFG, s2);

    // main stream: seg_attn (needs GEMM1a outputs + sort/shadows via evSort)
    cudaStreamWaitEvent(0, evSort, 0);
    seg_attn_kernel<<<(M + 7) / 8, 256>>>(chi, v_w, M);

    // main stream: phase-3 GEMMs (Uih, Uch, Uoh) on A = hhat
    {
        TcArgs ga;
        ga.A1 = p_hhat; ga.A2 = nullptr; ga.nW1 = 3; ga.nW2 = 0; ga.M = M;
        int slot[7] = {7, 8, 9, 7, 7, 7, 7};
        __half* cs[7] = {p_Uihh, p_Uchh, p_Uohh, p_Uihh, p_Uihh, p_Uihh, p_Uihh};
        for (int i = 0; i < 7; i++) {
            ga.wh[i] = p_wh + slot[i] * 32768;
            ga.b[i] = nullptr;
            ga.C[i] = cs[i];
        }
        gemm_mma<<<mtiles, NT, S_TOT1>>>(ga);
    }

    // join: epilogue needs GEMM3 (main), plus sumfc + Wix/Wcx/Wox via evFG (covers GEMM1b)
    cudaStreamWaitEvent(0, evFG, 0);
    const int n4 = M * Hd / 4;
    epilogue_kernel<<<(n4 + 255) / 256, 256>>>(outh, outc, n4);
}